// round 1
// baseline (speedup 1.0000x reference)
#include <cuda_runtime.h>

#define B_   32
#define CI_  64
#define CO_  64
#define Hh   128
#define Ww   128
#define NE   5
#define NT   10

#define OCB  8     // output channels per block
#define CIB  4     // input channels per smem chunk
#define TS   32    // spatial tile (32x32)

// Scratch (no cudaMalloc allowed)
__device__ float g_gate[B_ * NE * CO_];                 // [b][e][o]
__device__ float g_wsyn[(size_t)B_ * CO_ * CI_ * 25];   // [b][o][i][25]

// ---------------------------------------------------------------------------
// Packed fp32x2 helpers (Blackwell dual-rate fp32)
// ---------------------------------------------------------------------------
__device__ __forceinline__ unsigned long long pack2(float lo, float hi) {
    unsigned long long r;
    asm("mov.b64 %0, {%1, %2};" : "=l"(r) : "f"(lo), "f"(hi));
    return r;
}
__device__ __forceinline__ void unpack2(unsigned long long v, float& lo, float& hi) {
    asm("mov.b64 {%0, %1}, %2;" : "=f"(lo), "=f"(hi) : "l"(v));
}
__device__ __forceinline__ void ffma2(unsigned long long& d,
                                      unsigned long long a,
                                      unsigned long long b) {
    asm("fma.rn.f32x2 %0, %1, %2, %0;" : "+l"(d) : "l"(a), "l"(b));
}

// ---------------------------------------------------------------------------
// 1) Gate: logits = gate_w[:, task] + gate_b, softmax over experts
// ---------------------------------------------------------------------------
__global__ void gate_kernel(const int* __restrict__ task,
                            const float* __restrict__ gw,
                            const float* __restrict__ gb) {
    int b = blockIdx.x;
    int o = threadIdx.x;
    int t = task[b];
    float l[NE];
    float m = -1e30f;
#pragma unroll
    for (int e = 0; e < NE; e++) {
        int eo = e * CO_ + o;
        l[e] = gw[eo * NT + t] + gb[eo];
        m = fmaxf(m, l[e]);
    }
    float s = 0.f;
#pragma unroll
    for (int e = 0; e < NE; e++) { l[e] = expf(l[e] - m); s += l[e]; }
    float inv = 1.f / s;
#pragma unroll
    for (int e = 0; e < NE; e++) g_gate[(b * NE + e) * CO_ + o] = l[e] * inv;
}

// ---------------------------------------------------------------------------
// 2) Per-sample kernel synthesis: w[b,o,i,ky,kx] = sum_e g[b,e,o]*expert_e
// ---------------------------------------------------------------------------
__global__ void synth_kernel(const float* __restrict__ w5,
                             const float* __restrict__ w3,
                             const float* __restrict__ w1,
                             const float* __restrict__ wa3,
                             const float* __restrict__ wa5) {
    int o = blockIdx.x;
    int b = blockIdx.y;
    int i = threadIdx.x;

    float g0 = g_gate[(b * NE + 0) * CO_ + o];
    float g1 = g_gate[(b * NE + 1) * CO_ + o];
    float g2 = g_gate[(b * NE + 2) * CO_ + o];
    float g3 = g_gate[(b * NE + 3) * CO_ + o];
    float g4 = g_gate[(b * NE + 4) * CO_ + o];

    const float* W5 = w5 + ((size_t)o * CI_ + i) * 25;
    const float* W3 = w3 + ((size_t)o * CI_ + i) * 9;
    float c1 = g2 * w1[o * CI_ + i];
    float a3 = g3 * wa3[o * CI_ + i] * (1.f / 9.f);
    float a5 = g4 * wa5[o * CI_ + i] * (1.f / 25.f);

    float* outp = g_wsyn + (((size_t)b * CO_ + o) * CI_ + i) * 25;
#pragma unroll
    for (int ky = 0; ky < 5; ky++) {
#pragma unroll
        for (int kx = 0; kx < 5; kx++) {
            float v = g0 * W5[ky * 5 + kx] + a5;
            if (ky >= 1 && ky <= 3 && kx >= 1 && kx <= 3)
                v += g1 * W3[(ky - 1) * 3 + (kx - 1)] + a3;
            if (ky == 2 && kx == 2) v += c1;
            outp[ky * 5 + kx] = v;
        }
    }
}

// ---------------------------------------------------------------------------
// 3) Direct conv: block = (b, 8 oc, 32x32 tile). Packed f32x2 inner loop.
// ---------------------------------------------------------------------------
__global__ __launch_bounds__(256) void conv_kernel(const float* __restrict__ x,
                                                   float* __restrict__ y) {
    __shared__ float  sx[CIB][36][36];        // 20736 B
    __shared__ float2 sw[OCB][CIB][25];       // 6400 B (weight duplicated into both halves)

    int tileX = blockIdx.x;                   // 0..3
    int tileY = blockIdx.y;                   // 0..3
    int bz    = blockIdx.z;                   // b*8 + ocb
    int b     = bz >> 3;
    int ocb   = bz & 7;

    int tid = threadIdx.x;
    int px  = tid & 31;           // column within tile (lane)
    int py0 = (tid >> 5) << 2;    // base row within tile (warp id * 4)

    int baseX = tileX * TS;
    int baseY = tileY * TS;

    const float* xb = x + (size_t)b * CI_ * Hh * Ww;

    unsigned long long acc[OCB][2];
#pragma unroll
    for (int oc = 0; oc < OCB; oc++) { acc[oc][0] = 0ull; acc[oc][1] = 0ull; }

    for (int c0 = 0; c0 < CI_; c0 += CIB) {
        // --- cooperative x-tile load (with halo 2, zero fill OOB) ---
        for (int idx = tid; idx < CIB * 36 * 36; idx += 256) {
            int ci  = idx / 1296;
            int rem = idx - ci * 1296;
            int yy  = rem / 36;
            int xx  = rem - yy * 36;
            int gy  = baseY + yy - 2;
            int gx  = baseX + xx - 2;
            float v = 0.f;
            if ((unsigned)gy < (unsigned)Hh && (unsigned)gx < (unsigned)Ww)
                v = xb[((size_t)(c0 + ci) * Hh + gy) * Ww + gx];
            sx[ci][yy][xx] = v;
        }
        // --- weight load (duplicated into float2 for packed FMA) ---
        for (int idx = tid; idx < OCB * CIB * 25; idx += 256) {
            int oc  = idx / (CIB * 25);
            int rem = idx - oc * (CIB * 25);
            int ci  = rem / 25;
            int k   = rem - ci * 25;
            float w = g_wsyn[(((size_t)b * CO_ + (ocb * OCB + oc)) * CI_ + (c0 + ci)) * 25 + k];
            sw[oc][ci][k] = make_float2(w, w);
        }
        __syncthreads();

        // --- compute ---
#pragma unroll
        for (int ci = 0; ci < CIB; ci++) {
#pragma unroll
            for (int kx = 0; kx < 5; kx++) {
                float xc[8];
#pragma unroll
                for (int r = 0; r < 8; r++)
                    xc[r] = sx[ci][py0 + r][px + kx];
#pragma unroll
                for (int ky = 0; ky < 5; ky++) {
                    unsigned long long a0 = pack2(xc[ky],     xc[ky + 1]);
                    unsigned long long a1 = pack2(xc[ky + 2], xc[ky + 3]);
#pragma unroll
                    for (int oc = 0; oc < OCB; oc++) {
                        unsigned long long w2 =
                            *reinterpret_cast<const unsigned long long*>(&sw[oc][ci][ky * 5 + kx]);
                        ffma2(acc[oc][0], a0, w2);
                        ffma2(acc[oc][1], a1, w2);
                    }
                }
            }
        }
        __syncthreads();
    }

    // --- writeback: 8 oc x 4 rows per thread ---
#pragma unroll
    for (int oc = 0; oc < OCB; oc++) {
        float v0, v1, v2, v3;
        unpack2(acc[oc][0], v0, v1);
        unpack2(acc[oc][1], v2, v3);
        int o = ocb * OCB + oc;
        size_t base = (((size_t)b * CO_ + o) * Hh + (baseY + py0)) * Ww + baseX + px;
        y[base + 0 * Ww] = v0;
        y[base + 1 * Ww] = v1;
        y[base + 2 * Ww] = v2;
        y[base + 3 * Ww] = v3;
    }
}

// ---------------------------------------------------------------------------
// 4) Optional tail: second tuple element (task_id) cast to output dtype
// ---------------------------------------------------------------------------
__global__ void tail_kernel(const int* __restrict__ task, float* __restrict__ out,
                            int extra) {
    int j = threadIdx.x;
    if (j < extra && j < B_)
        out[(size_t)B_ * CO_ * Hh * Ww + j] = (float)task[j];
}

// ---------------------------------------------------------------------------
extern "C" void kernel_launch(void* const* d_in, const int* in_sizes, int n_in,
                              void* d_out, int out_size) {
    const float* x    = (const float*)d_in[0];
    const int*   task = (const int*)d_in[1];
    const float* gw   = (const float*)d_in[2];
    const float* gb   = (const float*)d_in[3];
    const float* w5   = (const float*)d_in[4];
    const float* w3   = (const float*)d_in[5];
    const float* w1   = (const float*)d_in[6];
    const float* wa3  = (const float*)d_in[7];
    const float* wa5  = (const float*)d_in[8];
    float* out = (float*)d_out;

    gate_kernel<<<B_, CO_>>>(task, gw, gb);
    synth_kernel<<<dim3(CO_, B_), CI_>>>(w5, w3, w1, wa3, wa5);
    conv_kernel<<<dim3(Hh / TS, Ww / TS, B_ * (CO_ / OCB)), 256>>>(x, out);

    int ymain = B_ * CO_ * Hh * Ww;
    int extra = out_size - ymain;
    if (extra > 0) tail_kernel<<<1, 64>>>(task, out, extra);
}

// round 3
// speedup vs baseline: 13.6285x; 13.6285x over previous
#include <cuda_runtime.h>
#include <cuda_fp16.h>
#include <cstdint>

#define B_  32
#define CI_ 64
#define CO_ 64
#define Hh  128
#define Ww  128
#define NE  5
#define NT  10

// SMEM layout (bytes from dynamic base)
// A: [slot 6][x 132][ci 16 (+8 pad)] fp16, pixel stride 48B -> 38016 B
// B: [tap 25][unit 128 x 16B, XOR-swizzled] -> 51200 B
#define SA_BYTES   38016
#define SB_OFF     38016
#define SMEM_TOTAL 89216
#define PX_STRIDE  24           // halfs per pixel row (48B)

// B operand prepack: [b][chunk4][tap25][o64][ci16] fp16 = 3,276,800 halfs
__device__ uint4 g_wB4[409600];

// ---------------------------------------------------------------------------
static __device__ __forceinline__ uint32_t smem_u32(const void* p) {
    uint32_t a;
    asm("{ .reg .u64 t; cvta.to.shared.u64 t, %1; cvt.u32.u64 %0, t; }"
        : "=r"(a) : "l"(p));
    return a;
}
static __device__ __forceinline__ void ldsm_x4(uint32_t* a, uint32_t addr) {
    asm volatile("ldmatrix.sync.aligned.m8n8.x4.shared.b16 {%0,%1,%2,%3}, [%4];"
                 : "=r"(a[0]), "=r"(a[1]), "=r"(a[2]), "=r"(a[3]) : "r"(addr));
}
static __device__ __forceinline__ void ldsm_x2(uint32_t* b, uint32_t addr) {
    asm volatile("ldmatrix.sync.aligned.m8n8.x2.shared.b16 {%0,%1}, [%2];"
                 : "=r"(b[0]), "=r"(b[1]) : "r"(addr));
}
static __device__ __forceinline__ void mma16816(float* d, const uint32_t* a,
                                                const uint32_t* b) {
    asm volatile(
        "mma.sync.aligned.m16n8k16.row.col.f32.f16.f16.f32 "
        "{%0,%1,%2,%3}, {%4,%5,%6,%7}, {%8,%9}, {%0,%1,%2,%3};"
        : "+f"(d[0]), "+f"(d[1]), "+f"(d[2]), "+f"(d[3])
        : "r"(a[0]), "r"(a[1]), "r"(a[2]), "r"(a[3]), "r"(b[0]), "r"(b[1]));
}

// ---------------------------------------------------------------------------
// synth: gate softmax + per-sample 5x5 kernel synthesis -> fp16 B pack
// g_wB layout: [b][chunk][tap][o][ci16]
// ---------------------------------------------------------------------------
__global__ void synth_kernel(const int* __restrict__ task,
                             const float* __restrict__ gw,
                             const float* __restrict__ gb,
                             const float* __restrict__ w5,
                             const float* __restrict__ w3,
                             const float* __restrict__ w1,
                             const float* __restrict__ wa3,
                             const float* __restrict__ wa5) {
    int o = blockIdx.x;
    int b = blockIdx.y;
    int i = threadIdx.x;     // ci 0..63
    int t = task[b];

    float l[NE];
    float m = -1e30f;
#pragma unroll
    for (int e = 0; e < NE; e++) {
        int eo = e * CO_ + o;
        l[e] = gw[eo * NT + t] + gb[eo];
        m = fmaxf(m, l[e]);
    }
    float s = 0.f;
#pragma unroll
    for (int e = 0; e < NE; e++) { l[e] = expf(l[e] - m); s += l[e]; }
    float inv = 1.f / s;
    float g0 = l[0] * inv, g1 = l[1] * inv, g2 = l[2] * inv,
          g3 = l[3] * inv, g4 = l[4] * inv;

    const float* W5 = w5 + ((size_t)o * CI_ + i) * 25;
    const float* W3 = w3 + ((size_t)o * CI_ + i) * 9;
    float c1 = g2 * w1[o * CI_ + i];
    float a3 = g3 * wa3[o * CI_ + i] * (1.f / 9.f);
    float a5 = g4 * wa5[o * CI_ + i] * (1.f / 25.f);

    int c4 = i >> 4;
    int cl = i & 15;
    __half* wb = (__half*)g_wB4;
    size_t base = (((size_t)(b * 4 + c4) * 25) * 64 + o) * 16 + cl;

#pragma unroll
    for (int ky = 0; ky < 5; ky++) {
#pragma unroll
        for (int kx = 0; kx < 5; kx++) {
            float v = g0 * W5[ky * 5 + kx] + a5;
            if (ky >= 1 && ky <= 3 && kx >= 1 && kx <= 3)
                v += g1 * W3[(ky - 1) * 3 + (kx - 1)] + a3;
            if (ky == 2 && kx == 2) v += c1;
            wb[base + (size_t)(ky * 5 + kx) * 1024] = __float2half_rn(v);
        }
    }
}

// ---------------------------------------------------------------------------
// conv: HMMA implicit GEMM. CTA = (b, 2-row group): M=256 px, N=64 oc,
// K = 4 ci-chunks x 25 taps x 16.
// ---------------------------------------------------------------------------
__global__ __launch_bounds__(256, 2) void conv_kernel(const float* __restrict__ x,
                                                      float* __restrict__ y) {
    extern __shared__ char smem[];
    uint32_t sA = smem_u32(smem);
    uint32_t sB = sA + SB_OFF;

    int tid = threadIdx.x;
    int w   = tid >> 5;
    int l   = tid & 31;
    int bid = blockIdx.x;
    int b   = bid >> 6;
    int y0  = (bid & 63) << 1;

    // A ldmatrix lane base addresses (s = 0,1 m-halves of warp tile m32)
    uint32_t aBase[2];
    {
        int row = l & 15;
        int kq  = (l >> 4) & 1;            // k-half (+16B)
#pragma unroll
        for (int s = 0; s < 2; s++) {
            int slot = w >> 2;
            int sx   = (w & 3) * 32 + s * 16 + row;
            aBase[s] = sA + (uint32_t)((slot * 132 + sx) * 48) + kq * 16;
        }
    }
    // B ldmatrix lane base offsets (within a tap block), XOR swizzle
    uint32_t bOff[8];
    {
        int ol = l & 7;
        int kh = (l >> 3) & 1;
#pragma unroll
        for (int j = 0; j < 8; j++) {
            int u    = (j * 8 + ol) * 2 + kh;
            int phys = u ^ ((u >> 3) & 1);
            bOff[j]  = (uint32_t)(phys * 16);
        }
    }

    float acc[2][8][4];
#pragma unroll
    for (int s = 0; s < 2; s++)
#pragma unroll
        for (int j = 0; j < 8; j++)
#pragma unroll
            for (int k = 0; k < 4; k++) acc[s][j][k] = 0.f;

    const float* xb = x + (size_t)b * CI_ * Hh * Ww;

    for (int c = 0; c < 4; c++) {
        // ---- B chunk copy: contiguous 51200B with 16B-unit XOR swizzle ----
        {
            const uint4* src = g_wB4 + (size_t)(b * 4 + c) * 3200;
            uint4* dst = (uint4*)(smem + SB_OFF);
            for (int u = tid; u < 3200; u += 256) {
                int tap = u >> 7;
                int wi  = u & 127;
                int ph  = wi ^ ((wi >> 3) & 1);
                dst[(tap << 7) + ph] = src[u];
            }
        }
        // ---- A chunk load: fp32 -> fp16, [slot][x][ci16] ----
        for (int cell = tid; cell < 792; cell += 256) {
            int slot = cell / 132;
            int xx   = cell - slot * 132;
            int gy   = y0 - 2 + slot;
            int gx   = xx - 2;
            bool ok  = ((unsigned)gy < (unsigned)Hh) && ((unsigned)gx < (unsigned)Ww);
            const float* px = xb + ((size_t)(c * 16) * Hh + gy) * Ww + gx;
            __half2 hv[8];
#pragma unroll
            for (int q = 0; q < 8; q++) {
                float f0 = ok ? px[(size_t)(2 * q) * (Hh * Ww)] : 0.f;
                float f1 = ok ? px[(size_t)(2 * q + 1) * (Hh * Ww)] : 0.f;
                hv[q] = __floats2half2_rn(f0, f1);
            }
            __half* dp = (__half*)smem + (size_t)(slot * 132 + xx) * PX_STRIDE;
            *(uint4*)(dp)     = *(const uint4*)(&hv[0]);
            *(uint4*)(dp + 8) = *(const uint4*)(&hv[4]);
        }
        __syncthreads();

        // ---- compute 25 taps ----
#pragma unroll
        for (int ky = 0; ky < 5; ky++) {
#pragma unroll
            for (int kx = 0; kx < 5; kx++) {
                uint32_t ta = (uint32_t)((ky * 132 + kx) * 48);
                uint32_t tb = sB + (uint32_t)((ky * 5 + kx) * 2048);
                uint32_t af[2][4], bf[8][2];
                ldsm_x4(af[0], aBase[0] + ta);
                ldsm_x4(af[1], aBase[1] + ta);
#pragma unroll
                for (int j = 0; j < 8; j++) ldsm_x2(bf[j], tb + bOff[j]);
#pragma unroll
                for (int s = 0; s < 2; s++)
#pragma unroll
                    for (int j = 0; j < 8; j++) mma16816(acc[s][j], af[s], bf[j]);
            }
        }
        __syncthreads();
    }

    // ---- epilogue: stage through smem (padded rows), coalesced writeout ----
    float* sO = (float*)smem;   // [64 oc][260] floats
#pragma unroll
    for (int s = 0; s < 2; s++)
#pragma unroll
        for (int j = 0; j < 8; j++) {
            int r0 = w * 32 + s * 16 + (l >> 2);
            int cc = j * 8 + ((l & 3) << 1);
            sO[cc * 260 + r0]           = acc[s][j][0];
            sO[(cc + 1) * 260 + r0]     = acc[s][j][1];
            sO[cc * 260 + r0 + 8]       = acc[s][j][2];
            sO[(cc + 1) * 260 + r0 + 8] = acc[s][j][3];
        }
    __syncthreads();

    {
        int ry = y0 + (tid >> 7);
        int rx = tid & 127;
        float* yp = y + (size_t)b * CO_ * Hh * Ww + (size_t)ry * Ww + rx;
#pragma unroll 8
        for (int o = 0; o < 64; o++)
            yp[(size_t)o * (Hh * Ww)] = sO[o * 260 + tid];
    }
}

// ---------------------------------------------------------------------------
__global__ void tail_kernel(const int* __restrict__ task, float* __restrict__ out,
                            int extra) {
    int j = threadIdx.x;
    if (j < extra && j < B_)
        out[(size_t)B_ * CO_ * Hh * Ww + j] = (float)task[j];
}

// ---------------------------------------------------------------------------
extern "C" void kernel_launch(void* const* d_in, const int* in_sizes, int n_in,
                              void* d_out, int out_size) {
    const float* x    = (const float*)d_in[0];
    const int*   task = (const int*)d_in[1];
    const float* gw   = (const float*)d_in[2];
    const float* gb   = (const float*)d_in[3];
    const float* w5   = (const float*)d_in[4];
    const float* w3   = (const float*)d_in[5];
    const float* w1   = (const float*)d_in[6];
    const float* wa3  = (const float*)d_in[7];
    const float* wa5  = (const float*)d_in[8];
    float* out = (float*)d_out;

    cudaFuncSetAttribute(conv_kernel, cudaFuncAttributeMaxDynamicSharedMemorySize,
                         SMEM_TOTAL);

    synth_kernel<<<dim3(CO_, B_), CI_>>>(task, gw, gb, w5, w3, w1, wa3, wa5);

    int ymain = B_ * CO_ * Hh * Ww;
    int extra = out_size - ymain;
    if (extra > 0) tail_kernel<<<1, 64>>>(task, out, extra);

    conv_kernel<<<B_ * 64, 256, SMEM_TOTAL>>>(x, out);
}